// round 13
// baseline (speedup 1.0000x reference)
#include <cuda_runtime.h>
#include <cuda_bf16.h>
#include <cstring>

#define Bz 32
#define Sz 64
#define Tz 64
#define Ez 512
#define Hz 1024
#define VTz 32000

// ---------------- device scratch (no dynamic alloc allowed) ----------------
__device__ float g_enc_out[Bz * Sz * Hz];     // encoder hidden states (B,S,H)
__device__ float g_encpart[Bz * Sz * Hz];     // enc_out @ Wa2^T + attn_b
__device__ float g_h[2][Bz * Hz];             // double-buffered hidden
__device__ float g_c[Bz * Hz];                // cell state (in-place safe)
__device__ float g_hpart[Bz * Hz];            // h @ Wa1^T
__device__ float g_scores[Bz * Sz];
__device__ float g_xin[Bz * (Ez + Hz)];       // decoder lstm input [emb | ctx]
__device__ float g_hall[(Tz - 1) * Bz * Hz];  // all decoder h_t for final GEMM

typedef unsigned long long u64;

// packed dual-FMA (sm_100+): 2x fp32 MAC per instruction
__device__ __forceinline__ void fma2(u64 &d, u64 a, u64 b) {
    asm("fma.rn.f32x2 %0, %1, %2, %0;" : "+l"(d) : "l"(a), "l"(b));
}
__device__ __forceinline__ float2 up(u64 v) {
    float2 t; memcpy(&t, &v, 8); return t;
}
__device__ __forceinline__ u64 pk(float x, float y) {
    float2 t = make_float2(x, y); u64 r; memcpy(&r, &t, 8); return r;
}
__device__ __forceinline__ float sigf(float x) { return 1.0f / (1.0f + __expf(-x)); }
__device__ __forceinline__ float tanha(float x) {
    float y; asm("tanh.approx.f32 %0, %1;" : "=f"(y) : "f"(x)); return y;
}

// ---------------------------------------------------------------------------
// init: zero h0, c0 and the t=0 output slice (out is poisoned by harness)
// ---------------------------------------------------------------------------
__global__ void k_init(float *__restrict__ out) {
    int idx = blockIdx.x * blockDim.x + threadIdx.x;
    int stride = gridDim.x * blockDim.x;
    for (int i = idx; i < Bz * Hz; i += stride) {
        g_h[0][i] = 0.f;
        g_c[i] = 0.f;
    }
    for (int i = idx; i < Bz * VTz; i += stride) {
        int bb = i / VTz, vv = i - bb * VTz;
        out[(size_t)bb * Tz * VTz + vv] = 0.f;
    }
}

// ---------------------------------------------------------------------------
// one LSTM step: thread = (batch lane, gate column j), computes all 4 gates.
// block 256 thr = 32 lanes x 8 j-warps, grid 128 -> H=1024 columns.
// mode 0: encoder (x = enc_emb[src[b][step]]), also writes g_enc_out
// mode 1: decoder (x = g_xin), also writes g_hall[step]
// ---------------------------------------------------------------------------
__global__ void __launch_bounds__(256) k_lstm(
    const float *__restrict__ emb, const int *__restrict__ tok,
    const float *__restrict__ Wih, const float *__restrict__ Whh,
    const float *__restrict__ bih, const float *__restrict__ bhh,
    int Kx, int par, int mode, int step) {
    __shared__ float xs[32][260];  // padded: conflict-free LDS.128
    __shared__ const float *rowp[32];
    int tid = threadIdx.x, lane = tid & 31, w = tid >> 5;
    int j = blockIdx.x * 8 + w;
    u64 a0 = 0, a1 = 0, a2 = 0, a3 = 0;
    const float *hin = g_h[par];

    for (int seg = 0; seg < 2; seg++) {
        const float *Wb = seg ? Whh : Wih;
        int K = seg ? Hz : Kx;
        __syncthreads();
        if (tid < 32) {
            if (seg)
                rowp[tid] = hin + tid * Hz;
            else if (mode == 0)
                rowp[tid] = emb + (size_t)tok[tid * Sz + step] * Ez;
            else
                rowp[tid] = g_xin + (size_t)tid * (Ez + Hz);
        }
        const float *w0 = Wb + (size_t)(0 * Hz + j) * K;
        const float *w1 = Wb + (size_t)(1 * Hz + j) * K;
        const float *w2 = Wb + (size_t)(2 * Hz + j) * K;
        const float *w3 = Wb + (size_t)(3 * Hz + j) * K;
        for (int k0 = 0; k0 < K; k0 += 256) {
            __syncthreads();
            for (int i = tid; i < 32 * 64; i += 256) {
                int bb = i >> 6, kk = i & 63;
                *(float4 *)&xs[bb][kk * 4] = *(const float4 *)(rowp[bb] + k0 + kk * 4);
            }
            __syncthreads();
            const ulonglong2 *p0 = (const ulonglong2 *)(w0 + k0);
            const ulonglong2 *p1 = (const ulonglong2 *)(w1 + k0);
            const ulonglong2 *p2 = (const ulonglong2 *)(w2 + k0);
            const ulonglong2 *p3 = (const ulonglong2 *)(w3 + k0);
#pragma unroll 8
            for (int kk = 0; kk < 64; kk++) {
                ulonglong2 xv = *(const ulonglong2 *)&xs[lane][kk * 4];
                ulonglong2 q;
                q = __ldg(p0 + kk); fma2(a0, xv.x, q.x); fma2(a0, xv.y, q.y);
                q = __ldg(p1 + kk); fma2(a1, xv.x, q.x); fma2(a1, xv.y, q.y);
                q = __ldg(p2 + kk); fma2(a2, xv.x, q.x); fma2(a2, xv.y, q.y);
                q = __ldg(p3 + kk); fma2(a3, xv.x, q.x); fma2(a3, xv.y, q.y);
            }
        }
    }
    float2 t0 = up(a0), t1 = up(a1), t2 = up(a2), t3 = up(a3);
    float gi = t0.x + t0.y + bih[j] + bhh[j];
    float gf = t1.x + t1.y + bih[Hz + j] + bhh[Hz + j];
    float gg = t2.x + t2.y + bih[2 * Hz + j] + bhh[2 * Hz + j];
    float go = t3.x + t3.y + bih[3 * Hz + j] + bhh[3 * Hz + j];
    int idx = lane * Hz + j;
    float cn = sigf(gf) * g_c[idx] + sigf(gi) * tanhf(gg);
    g_c[idx] = cn;
    float hn = sigf(go) * tanhf(cn);
    g_h[par ^ 1][idx] = hn;
    if (mode == 0)
        g_enc_out[((size_t)lane * Sz + step) * Hz + j] = hn;
    else
        g_hall[((size_t)step * Bz + lane) * Hz + j] = hn;
}

// ---------------------------------------------------------------------------
// hpart[b][j] = sum_k h[b][k] * attn_W[j][k]  (first-H half of attn_W rows)
// ---------------------------------------------------------------------------
__global__ void __launch_bounds__(256) k_hpart(const float *__restrict__ attn_W, int par) {
    __shared__ float xs[32][260];
    int tid = threadIdx.x, lane = tid & 31, w = tid >> 5;
    int j = blockIdx.x * 8 + w;
    const float *hin = g_h[par];
    const float *wr = attn_W + (size_t)j * (2 * Hz);
    u64 acc = 0;
    for (int k0 = 0; k0 < Hz; k0 += 256) {
        __syncthreads();
        for (int i = tid; i < 32 * 64; i += 256) {
            int bb = i >> 6, kk = i & 63;
            *(float4 *)&xs[bb][kk * 4] =
                *(const float4 *)(hin + (size_t)bb * Hz + k0 + kk * 4);
        }
        __syncthreads();
        const ulonglong2 *p = (const ulonglong2 *)(wr + k0);
#pragma unroll 8
        for (int kk = 0; kk < 64; kk++) {
            ulonglong2 xv = *(const ulonglong2 *)&xs[lane][kk * 4];
            ulonglong2 q = __ldg(p + kk);
            fma2(acc, xv.x, q.x);
            fma2(acc, xv.y, q.y);
        }
    }
    float2 t = up(acc);
    g_hpart[lane * Hz + j] = t.x + t.y;
}

// ---------------------------------------------------------------------------
// scores[b][s] = sum_j tanh(hpart[b][j] + encpart[b][s][j]) * v[j]
// one warp per (b,s) pair; MUFU-pipe tanh.approx
// ---------------------------------------------------------------------------
__global__ void __launch_bounds__(256) k_score(const float *__restrict__ v) {
    int w = blockIdx.x * 8 + (threadIdx.x >> 5);
    int lane = threadIdx.x & 31;
    int b = w >> 6, s = w & 63;
    const float *ep = g_encpart + ((size_t)b * Sz + s) * Hz;
    const float *hp = g_hpart + (size_t)b * Hz;
    float acc = 0.f;
    for (int k = lane * 4; k < Hz; k += 128) {
        float4 e = *(const float4 *)(ep + k);
        float4 h = *(const float4 *)(hp + k);
        float4 vv = *(const float4 *)(v + k);
        acc += tanha(h.x + e.x) * vv.x + tanha(h.y + e.y) * vv.y +
               tanha(h.z + e.z) * vv.z + tanha(h.w + e.w) * vv.w;
    }
#pragma unroll
    for (int o = 16; o; o >>= 1) acc += __shfl_xor_sync(0xffffffffu, acc, o);
    if (lane == 0) g_scores[b * Sz + s] = acc;
}

// ---------------------------------------------------------------------------
// softmax over S, context = attn @ enc_out, xin = [dec_emb[tok] | ctx]
// one block per batch element
// ---------------------------------------------------------------------------
__global__ void __launch_bounds__(256) k_ctx(const float *__restrict__ dec_emb,
                                             const int *__restrict__ tgt, int d) {
    __shared__ float sm[64];
    int b = blockIdx.x, tid = threadIdx.x;
    if (tid < 64) sm[tid] = g_scores[b * Sz + tid];
    __syncthreads();
    if (tid == 0) {
        float m = sm[0];
        for (int i = 1; i < 64; i++) m = fmaxf(m, sm[i]);
        float ssum = 0.f;
        for (int i = 0; i < 64; i++) {
            float e = __expf(sm[i] - m);
            sm[i] = e;
            ssum += e;
        }
        float inv = 1.0f / ssum;
        for (int i = 0; i < 64; i++) sm[i] *= inv;
    }
    __syncthreads();
    const float *eb = g_enc_out + (size_t)b * Sz * Hz;
    int h0 = tid * 4;
    float4 acc = make_float4(0.f, 0.f, 0.f, 0.f);
    for (int s = 0; s < 64; s++) {
        float a = sm[s];
        float4 e = *(const float4 *)(eb + (size_t)s * Hz + h0);
        acc.x += a * e.x;
        acc.y += a * e.y;
        acc.z += a * e.z;
        acc.w += a * e.w;
    }
    *(float4 *)(g_xin + (size_t)b * (Ez + Hz) + Ez + h0) = acc;
    if (tid < Ez / 4) {
        int tk = tgt[b * Tz + d];
        *(float4 *)(g_xin + (size_t)b * (Ez + Hz) + tid * 4) =
            *(const float4 *)(dec_emb + (size_t)tk * Ez + tid * 4);
    }
}

// ---------------------------------------------------------------------------
// SGEMM (NT): C[r][n] = bias[n] + sum_k A[r][k]*Bm[n][k]
// BM=BN=64, BK=16, 256 thr, 4x4 micro-tile, paired-k f32x2 accumulators.
// mode 0: A=g_enc_out -> g_encpart   (attention precompute)
// mode 1: A=g_hall    -> out, remapped (b, t+1, vocab)   (final fc)
// ---------------------------------------------------------------------------
__global__ void __launch_bounds__(256) k_sgemm(
    int M, int N, int K,
    const float *__restrict__ Bm, int ldb,
    const float *__restrict__ bias,
    float *__restrict__ outp, int mode) {
    __shared__ u64 As2[8 * 64];
    __shared__ u64 Bs2[8 * 64];
    const float *A = mode ? g_hall : g_enc_out;
    int tid = threadIdx.x;
    int col0 = blockIdx.x * 64, row0 = blockIdx.y * 64;
    int m = tid >> 2, kq = tid & 3;
    int tn = tid & 15, tr = tid >> 4;
    u64 acc[16];
#pragma unroll
    for (int i = 0; i < 16; i++) acc[i] = 0ull;

    for (int k0 = 0; k0 < K; k0 += 16) {
        __syncthreads();
        {
            int r = row0 + m;
            float4 v = make_float4(0.f, 0.f, 0.f, 0.f);
            if (r < M) v = *(const float4 *)(A + (size_t)r * Hz + k0 + kq * 4);
            As2[(2 * kq) * 64 + m] = pk(v.x, v.y);
            As2[(2 * kq + 1) * 64 + m] = pk(v.z, v.w);
            float4 u = *(const float4 *)(Bm + (size_t)(col0 + m) * ldb + k0 + kq * 4);
            Bs2[(2 * kq) * 64 + m] = pk(u.x, u.y);
            Bs2[(2 * kq + 1) * 64 + m] = pk(u.z, u.w);
        }
        __syncthreads();
#pragma unroll
        for (int kp = 0; kp < 8; kp++) {
            u64 a2[4], b2[4];
            *(ulonglong2 *)&a2[0] = *(const ulonglong2 *)&As2[kp * 64 + tr * 4];
            *(ulonglong2 *)&a2[2] = *(const ulonglong2 *)&As2[kp * 64 + tr * 4 + 2];
            *(ulonglong2 *)&b2[0] = *(const ulonglong2 *)&Bs2[kp * 64 + tn * 4];
            *(ulonglong2 *)&b2[2] = *(const ulonglong2 *)&Bs2[kp * 64 + tn * 4 + 2];
#pragma unroll
            for (int i = 0; i < 4; i++)
#pragma unroll
                for (int jj = 0; jj < 4; jj++)
                    fma2(acc[i * 4 + jj], a2[i], b2[jj]);
        }
    }
#pragma unroll
    for (int i = 0; i < 4; i++) {
        int row = row0 + tr * 4 + i;
        if (row >= M) continue;
#pragma unroll
        for (int jj = 0; jj < 4; jj++) {
            int col = col0 + tn * 4 + jj;
            float2 t = up(acc[i * 4 + jj]);
            float val = t.x + t.y + bias[col];
            if (mode == 0) {
                g_encpart[(size_t)row * Hz + col] = val;
            } else {
                int st = row >> 5, bb = row & 31;
                outp[((size_t)bb * Tz + (st + 1)) * VTz + col] = val;
            }
        }
    }
}

// ---------------------------------------------------------------------------
extern "C" void kernel_launch(void* const* d_in, const int* in_sizes, int n_in,
                              void* d_out, int out_size) {
    const int   *src     = (const int *)d_in[0];
    const int   *tgt     = (const int *)d_in[1];
    const float *enc_emb = (const float *)d_in[2];
    const float *enc_Wih = (const float *)d_in[3];
    const float *enc_Whh = (const float *)d_in[4];
    const float *enc_bih = (const float *)d_in[5];
    const float *enc_bhh = (const float *)d_in[6];
    const float *dec_emb = (const float *)d_in[7];
    const float *attn_W  = (const float *)d_in[8];
    const float *attn_b  = (const float *)d_in[9];
    const float *v_W     = (const float *)d_in[10];
    const float *dec_Wih = (const float *)d_in[11];
    const float *dec_Whh = (const float *)d_in[12];
    const float *dec_bih = (const float *)d_in[13];
    const float *dec_bhh = (const float *)d_in[14];
    const float *fc_W    = (const float *)d_in[15];
    const float *fc_b    = (const float *)d_in[16];
    float *out = (float *)d_out;

    k_init<<<512, 256>>>(out);

    // encoder: 64 sequential LSTM steps
    for (int s = 0; s < Sz; s++)
        k_lstm<<<128, 256>>>(enc_emb, src, enc_Wih, enc_Whh, enc_bih, enc_bhh,
                             Ez, s & 1, 0, s);

    // step-invariant attention precompute: encpart = enc_out @ Wa2^T + attn_b
    k_sgemm<<<dim3(Hz / 64, (Bz * Sz) / 64), 256>>>(
        Bz * Sz, Hz, Hz, attn_W + Hz, 2 * Hz, attn_b, nullptr, 0);

    // decoder: 63 teacher-forced steps
    for (int d = 0; d < Tz - 1; d++) {
        k_hpart<<<128, 256>>>(attn_W, d & 1);
        k_score<<<256, 256>>>(v_W);
        k_ctx<<<Bz, 256>>>(dec_emb, tgt, d);
        k_lstm<<<128, 256>>>(nullptr, nullptr, dec_Wih, dec_Whh, dec_bih,
                             dec_bhh, Ez + Hz, d & 1, 1, d);
    }

    // one big output projection: (63*32) x 32000 x 1024
    k_sgemm<<<dim3(VTz / 64, ((Tz - 1) * Bz + 63) / 64), 256>>>(
        (Tz - 1) * Bz, VTz, Hz, fc_W, Hz, fc_b, out, 1);
}

// round 14
// speedup vs baseline: 1.1990x; 1.1990x over previous
#include <cuda_runtime.h>
#include <cuda_bf16.h>
#include <cstring>

#define Bz 32
#define Sz 64
#define Tz 64
#define Ez 512
#define Hz 1024
#define VTz 32000
#define TK 128          // k-tile (both Kx and Hz are multiples of 128)

// ---------------- device scratch (no dynamic alloc allowed) ----------------
__device__ float g_enc_out[Bz * Sz * Hz];     // encoder hidden states (B,S,H)
__device__ float g_encpart[Bz * Sz * Hz];     // enc_out @ Wa2^T + attn_b
__device__ float g_h[2][Bz * Hz];             // double-buffered hidden
__device__ float g_c[Bz * Hz];                // cell state (in-place safe)
__device__ float g_hpart[Bz * Hz];            // h @ Wa1^T
__device__ float g_scores[Bz * Sz];
__device__ float g_xin[Bz * (Ez + Hz)];       // decoder lstm input [emb | ctx]
__device__ float g_hall[(Tz - 1) * Bz * Hz];  // all decoder h_t for final GEMM

typedef unsigned long long u64;

// packed dual-FMA (sm_100+): 2x fp32 MAC per instruction
__device__ __forceinline__ void fma2(u64 &d, u64 a, u64 b) {
    asm("fma.rn.f32x2 %0, %1, %2, %0;" : "+l"(d) : "l"(a), "l"(b));
}
__device__ __forceinline__ float2 up(u64 v) {
    float2 t; memcpy(&t, &v, 8); return t;
}
__device__ __forceinline__ u64 pk(float x, float y) {
    float2 t = make_float2(x, y); u64 r; memcpy(&r, &t, 8); return r;
}
__device__ __forceinline__ float sigf(float x) { return 1.0f / (1.0f + __expf(-x)); }
__device__ __forceinline__ float tanha(float x) {
    float y; asm("tanh.approx.f32 %0, %1;" : "=f"(y) : "f"(x)); return y;
}

// ---------------------------------------------------------------------------
// init: zero h0, c0 and the t=0 output slice (out is poisoned by harness)
// ---------------------------------------------------------------------------
__global__ void k_init(float *__restrict__ out) {
    int idx = blockIdx.x * blockDim.x + threadIdx.x;
    int stride = gridDim.x * blockDim.x;
    for (int i = idx; i < Bz * Hz; i += stride) {
        g_h[0][i] = 0.f;
        g_c[i] = 0.f;
    }
    for (int i = idx; i < Bz * VTz; i += stride) {
        int bb = i / VTz, vv = i - bb * VTz;
        out[(size_t)bb * Tz * VTz + vv] = 0.f;
    }
}

// ---------------------------------------------------------------------------
// one LSTM step, smem-staged weights.
// warp = (j-column, gate-pair): half 0 -> gates {i,f}, half 1 -> {g,o}.
// block = 8 warps = 4 j-columns x 2 halves; lanes = batch. grid 256 -> H=1024.
// Weights staged coalesced into smem each k-tile (kills broadcast-LDG waste);
// the 4-gate cell update is fused in-block via a smem gate exchange.
// mode 0: encoder (x = enc_emb[src[b][step]]), also writes g_enc_out
// mode 1: decoder (x = g_xin), also writes g_hall[step]
// ---------------------------------------------------------------------------
__global__ void __launch_bounds__(256) k_lstm(
    const float *__restrict__ emb, const int *__restrict__ tok,
    const float *__restrict__ Wih, const float *__restrict__ Whh,
    const float *__restrict__ bih, const float *__restrict__ bhh,
    int Kx, int par, int mode, int step) {
    __shared__ float4 xs[32 * 33];   // 32 batches x TK floats, pad 33 f4/row
    __shared__ float4 ws[16 * 33];   // 16 weight rows (4 j x 4 gates) x TK
    __shared__ float smg[4][4][33];  // [gate][j-local][lane] gate exchange
    __shared__ int stok[32];

    int tid = threadIdx.x, lane = tid & 31, w = tid >> 5;
    int jl = w >> 1, half = w & 1;
    int j0 = blockIdx.x * 4;
    int j = j0 + jl;
    const float *hin = g_h[par];

    if (mode == 0 && tid < 32) stok[tid] = tok[tid * Sz + step];

    u64 acc0 = 0, acc1 = 0;
    int nt0 = Kx / TK;            // tiles in segment 0 (x @ Wih)
    int ntot = nt0 + Hz / TK;     // + segment 1 (h @ Whh)

    for (int t = 0; t < ntot; ++t) {
        int seg = (t >= nt0);
        int koff = (seg ? (t - nt0) : t) * TK;
        int Kseg = seg ? Hz : Kx;
        const float *Wb = seg ? Whh : Wih;
        __syncthreads();
        // stage x tile: 32 rows x 32 float4 (each warp-iter: 1 row, coalesced)
        for (int i = tid; i < 32 * 32; i += 256) {
            int bb = i >> 5, c4 = i & 31;
            const float *xp;
            if (seg) xp = hin + bb * Hz + koff;
            else if (mode == 0) xp = emb + (size_t)stok[bb] * Ez + koff;
            else xp = g_xin + bb * (Ez + Hz) + koff;
            xs[bb * 33 + c4] = *(const float4 *)(xp + c4 * 4);
        }
        // stage weight tile: 16 rows x 32 float4, coalesced
        for (int i = tid; i < 16 * 32; i += 256) {
            int r = i >> 5, c4 = i & 31;
            int g = r & 3, jj = j0 + (r >> 2);
            ws[r * 33 + c4] = *(const float4 *)(
                Wb + (size_t)(g * Hz + jj) * Kseg + koff + c4 * 4);
        }
        __syncthreads();
        int r0 = jl * 4 + 2 * half;
        const ulonglong2 *xp2 = (const ulonglong2 *)(xs + lane * 33);
        const ulonglong2 *w0p = (const ulonglong2 *)(ws + r0 * 33);
        const ulonglong2 *w1p = (const ulonglong2 *)(ws + (r0 + 1) * 33);
#pragma unroll
        for (int kk = 0; kk < 32; ++kk) {
            ulonglong2 xv = xp2[kk];
            ulonglong2 a = w0p[kk];
            ulonglong2 b = w1p[kk];
            fma2(acc0, xv.x, a.x); fma2(acc0, xv.y, a.y);
            fma2(acc1, xv.x, b.x); fma2(acc1, xv.y, b.y);
        }
    }
    // fold f32x2 halves, add biases, exchange gates in-block
    float2 t0 = up(acc0), t1 = up(acc1);
    int ga = 2 * half, gb = 2 * half + 1;
    float va = t0.x + t0.y + bih[ga * Hz + j] + bhh[ga * Hz + j];
    float vb = t1.x + t1.y + bih[gb * Hz + j] + bhh[gb * Hz + j];
    __syncthreads();
    smg[ga][jl][lane] = va;
    smg[gb][jl][lane] = vb;
    __syncthreads();
    if (half == 0) {  // 4 warps do the cell update for their j
        float gi = smg[0][jl][lane], gf = smg[1][jl][lane];
        float gg = smg[2][jl][lane], go = smg[3][jl][lane];
        int idx = lane * Hz + j;
        float cn = sigf(gf) * g_c[idx] + sigf(gi) * tanhf(gg);
        g_c[idx] = cn;
        float hn = sigf(go) * tanhf(cn);
        g_h[par ^ 1][idx] = hn;
        if (mode == 0)
            g_enc_out[((size_t)lane * Sz + step) * Hz + j] = hn;
        else
            g_hall[((size_t)step * Bz + lane) * Hz + j] = hn;
    }
}

// ---------------------------------------------------------------------------
// hpart[b][j] = sum_k h[b][k] * attn_W[j][k]  (first-H half of attn_W rows)
// same smem-staged pattern; warp = j, block = 8 j, grid 128
// ---------------------------------------------------------------------------
__global__ void __launch_bounds__(256) k_hpart(const float *__restrict__ attn_W, int par) {
    __shared__ float4 xs[32 * 33];
    __shared__ float4 ws[8 * 33];
    int tid = threadIdx.x, lane = tid & 31, w = tid >> 5;
    int j0 = blockIdx.x * 8;
    int j = j0 + w;
    const float *hin = g_h[par];
    u64 acc = 0;

    for (int t = 0; t < Hz / TK; ++t) {
        int koff = t * TK;
        __syncthreads();
        for (int i = tid; i < 32 * 32; i += 256) {
            int bb = i >> 5, c4 = i & 31;
            xs[bb * 33 + c4] = *(const float4 *)(hin + bb * Hz + koff + c4 * 4);
        }
        for (int i = tid; i < 8 * 32; i += 256) {
            int r = i >> 5, c4 = i & 31;
            ws[r * 33 + c4] = *(const float4 *)(
                attn_W + (size_t)(j0 + r) * (2 * Hz) + koff + c4 * 4);
        }
        __syncthreads();
        const ulonglong2 *xp2 = (const ulonglong2 *)(xs + lane * 33);
        const ulonglong2 *wp2 = (const ulonglong2 *)(ws + w * 33);
#pragma unroll
        for (int kk = 0; kk < 32; ++kk) {
            ulonglong2 xv = xp2[kk];
            ulonglong2 a = wp2[kk];
            fma2(acc, xv.x, a.x);
            fma2(acc, xv.y, a.y);
        }
    }
    float2 t = up(acc);
    g_hpart[lane * Hz + j] = t.x + t.y;
}

// ---------------------------------------------------------------------------
// scores[b][s] = sum_j tanh(hpart[b][j] + encpart[b][s][j]) * v[j]
// one warp per (b,s) pair; MUFU-pipe tanh.approx
// ---------------------------------------------------------------------------
__global__ void __launch_bounds__(256) k_score(const float *__restrict__ v) {
    int w = blockIdx.x * 8 + (threadIdx.x >> 5);
    int lane = threadIdx.x & 31;
    int b = w >> 6, s = w & 63;
    const float *ep = g_encpart + ((size_t)b * Sz + s) * Hz;
    const float *hp = g_hpart + (size_t)b * Hz;
    float acc = 0.f;
    for (int k = lane * 4; k < Hz; k += 128) {
        float4 e = *(const float4 *)(ep + k);
        float4 h = *(const float4 *)(hp + k);
        float4 vv = *(const float4 *)(v + k);
        acc += tanha(h.x + e.x) * vv.x + tanha(h.y + e.y) * vv.y +
               tanha(h.z + e.z) * vv.z + tanha(h.w + e.w) * vv.w;
    }
#pragma unroll
    for (int o = 16; o; o >>= 1) acc += __shfl_xor_sync(0xffffffffu, acc, o);
    if (lane == 0) g_scores[b * Sz + s] = acc;
}

// ---------------------------------------------------------------------------
// softmax over S, context = attn @ enc_out, xin = [dec_emb[tok] | ctx]
// one block per batch element
// ---------------------------------------------------------------------------
__global__ void __launch_bounds__(256) k_ctx(const float *__restrict__ dec_emb,
                                             const int *__restrict__ tgt, int d) {
    __shared__ float sm[64];
    int b = blockIdx.x, tid = threadIdx.x;
    if (tid < 64) sm[tid] = g_scores[b * Sz + tid];
    __syncthreads();
    if (tid == 0) {
        float m = sm[0];
        for (int i = 1; i < 64; i++) m = fmaxf(m, sm[i]);
        float ssum = 0.f;
        for (int i = 0; i < 64; i++) {
            float e = __expf(sm[i] - m);
            sm[i] = e;
            ssum += e;
        }
        float inv = 1.0f / ssum;
        for (int i = 0; i < 64; i++) sm[i] *= inv;
    }
    __syncthreads();
    const float *eb = g_enc_out + (size_t)b * Sz * Hz;
    int h0 = tid * 4;
    float4 acc = make_float4(0.f, 0.f, 0.f, 0.f);
    for (int s = 0; s < 64; s++) {
        float a = sm[s];
        float4 e = *(const float4 *)(eb + (size_t)s * Hz + h0);
        acc.x += a * e.x;
        acc.y += a * e.y;
        acc.z += a * e.z;
        acc.w += a * e.w;
    }
    *(float4 *)(g_xin + (size_t)b * (Ez + Hz) + Ez + h0) = acc;
    if (tid < Ez / 4) {
        int tk = tgt[b * Tz + d];
        *(float4 *)(g_xin + (size_t)b * (Ez + Hz) + tid * 4) =
            *(const float4 *)(dec_emb + (size_t)tk * Ez + tid * 4);
    }
}

// ---------------------------------------------------------------------------
// SGEMM (NT): C[r][n] = bias[n] + sum_k A[r][k]*Bm[n][k]
// BM=BN=64, BK=16, 256 thr, 4x4 micro-tile, paired-k f32x2 accumulators.
// mode 0: A=g_enc_out -> g_encpart   (attention precompute)
// mode 1: A=g_hall    -> out, remapped (b, t+1, vocab)   (final fc)
// ---------------------------------------------------------------------------
__global__ void __launch_bounds__(256) k_sgemm(
    int M, int N, int K,
    const float *__restrict__ Bm, int ldb,
    const float *__restrict__ bias,
    float *__restrict__ outp, int mode) {
    __shared__ u64 As2[8 * 64];
    __shared__ u64 Bs2[8 * 64];
    const float *A = mode ? g_hall : g_enc_out;
    int tid = threadIdx.x;
    int col0 = blockIdx.x * 64, row0 = blockIdx.y * 64;
    int m = tid >> 2, kq = tid & 3;
    int tn = tid & 15, tr = tid >> 4;
    u64 acc[16];
#pragma unroll
    for (int i = 0; i < 16; i++) acc[i] = 0ull;

    for (int k0 = 0; k0 < K; k0 += 16) {
        __syncthreads();
        {
            int r = row0 + m;
            float4 v = make_float4(0.f, 0.f, 0.f, 0.f);
            if (r < M) v = *(const float4 *)(A + (size_t)r * Hz + k0 + kq * 4);
            As2[(2 * kq) * 64 + m] = pk(v.x, v.y);
            As2[(2 * kq + 1) * 64 + m] = pk(v.z, v.w);
            float4 u = *(const float4 *)(Bm + (size_t)(col0 + m) * ldb + k0 + kq * 4);
            Bs2[(2 * kq) * 64 + m] = pk(u.x, u.y);
            Bs2[(2 * kq + 1) * 64 + m] = pk(u.z, u.w);
        }
        __syncthreads();
#pragma unroll
        for (int kp = 0; kp < 8; kp++) {
            u64 a2[4], b2[4];
            *(ulonglong2 *)&a2[0] = *(const ulonglong2 *)&As2[kp * 64 + tr * 4];
            *(ulonglong2 *)&a2[2] = *(const ulonglong2 *)&As2[kp * 64 + tr * 4 + 2];
            *(ulonglong2 *)&b2[0] = *(const ulonglong2 *)&Bs2[kp * 64 + tn * 4];
            *(ulonglong2 *)&b2[2] = *(const ulonglong2 *)&Bs2[kp * 64 + tn * 4 + 2];
#pragma unroll
            for (int i = 0; i < 4; i++)
#pragma unroll
                for (int jj = 0; jj < 4; jj++)
                    fma2(acc[i * 4 + jj], a2[i], b2[jj]);
        }
    }
#pragma unroll
    for (int i = 0; i < 4; i++) {
        int row = row0 + tr * 4 + i;
        if (row >= M) continue;
#pragma unroll
        for (int jj = 0; jj < 4; jj++) {
            int col = col0 + tn * 4 + jj;
            float2 t = up(acc[i * 4 + jj]);
            float val = t.x + t.y + bias[col];
            if (mode == 0) {
                g_encpart[(size_t)row * Hz + col] = val;
            } else {
                int st = row >> 5, bb = row & 31;
                outp[((size_t)bb * Tz + (st + 1)) * VTz + col] = val;
            }
        }
    }
}

// ---------------------------------------------------------------------------
extern "C" void kernel_launch(void* const* d_in, const int* in_sizes, int n_in,
                              void* d_out, int out_size) {
    const int   *src     = (const int *)d_in[0];
    const int   *tgt     = (const int *)d_in[1];
    const float *enc_emb = (const float *)d_in[2];
    const float *enc_Wih = (const float *)d_in[3];
    const float *enc_Whh = (const float *)d_in[4];
    const float *enc_bih = (const float *)d_in[5];
    const float *enc_bhh = (const float *)d_in[6];
    const float *dec_emb = (const float *)d_in[7];
    const float *attn_W  = (const float *)d_in[8];
    const float *attn_b  = (const float *)d_in[9];
    const float *v_W     = (const float *)d_in[10];
    const float *dec_Wih = (const float *)d_in[11];
    const float *dec_Whh = (const float *)d_in[12];
    const float *dec_bih = (const float *)d_in[13];
    const float *dec_bhh = (const float *)d_in[14];
    const float *fc_W    = (const float *)d_in[15];
    const float *fc_b    = (const float *)d_in[16];
    float *out = (float *)d_out;

    k_init<<<512, 256>>>(out);

    // encoder: 64 sequential LSTM steps
    for (int s = 0; s < Sz; s++)
        k_lstm<<<256, 256>>>(enc_emb, src, enc_Wih, enc_Whh, enc_bih, enc_bhh,
                             Ez, s & 1, 0, s);

    // step-invariant attention precompute: encpart = enc_out @ Wa2^T + attn_b
    k_sgemm<<<dim3(Hz / 64, (Bz * Sz) / 64), 256>>>(
        Bz * Sz, Hz, Hz, attn_W + Hz, 2 * Hz, attn_b, nullptr, 0);

    // decoder: 63 teacher-forced steps
    for (int d = 0; d < Tz - 1; d++) {
        k_hpart<<<128, 256>>>(attn_W, d & 1);
        k_score<<<256, 256>>>(v_W);
        k_ctx<<<Bz, 256>>>(dec_emb, tgt, d);
        k_lstm<<<256, 256>>>(nullptr, nullptr, dec_Wih, dec_Whh, dec_bih,
                             dec_bhh, Ez + Hz, d & 1, 1, d);
    }

    // one big output projection: (63*32) x 32000 x 1024
    k_sgemm<<<dim3(VTz / 64, ((Tz - 1) * Bz + 63) / 64), 256>>>(
        (Tz - 1) * Bz, VTz, Hz, fc_W, Hz, fc_b, out, 1);
}

// round 16
// speedup vs baseline: 1.3717x; 1.1441x over previous
#include <cuda_runtime.h>
#include <cuda_bf16.h>
#include <cstring>

#define Bz 32
#define Sz 64
#define Tz 64
#define Ez 512
#define Hz 1024
#define VTz 32000
#define TK 128          // k-tile in floats (all K dims are multiples of 128)

// ---------------- device scratch (no dynamic alloc allowed) ----------------
__device__ float g_enc_out[Bz * Sz * Hz];     // encoder hidden states (B,S,H)
__device__ float g_encpart[Bz * Sz * Hz];     // enc_out @ Wa2^T + attn_b
__device__ float g_h[2][Bz * Hz];             // double-buffered hidden
__device__ float g_c[Bz * Hz];                // cell state (in-place safe)
__device__ float g_hpart[Bz * Hz];            // h @ Wa1^T
__device__ float g_scores[Bz * Sz];
__device__ float g_xin[Bz * (Ez + Hz)];       // decoder lstm input [emb | ctx]
__device__ float g_hall[(Tz - 1) * Bz * Hz];  // all decoder h_t for final GEMM

typedef unsigned long long u64;

// packed dual-FMA (sm_100+): 2x fp32 MAC per instruction
__device__ __forceinline__ void fma2(u64 &d, u64 a, u64 b) {
    asm("fma.rn.f32x2 %0, %1, %2, %0;" : "+l"(d) : "l"(a), "l"(b));
}
__device__ __forceinline__ float2 up(u64 v) {
    float2 t; memcpy(&t, &v, 8); return t;
}
__device__ __forceinline__ u64 pk(float x, float y) {
    float2 t = make_float2(x, y); u64 r; memcpy(&r, &t, 8); return r;
}
__device__ __forceinline__ float sigf(float x) { return 1.0f / (1.0f + __expf(-x)); }
__device__ __forceinline__ float tanha(float x) {
    float y; asm("tanh.approx.f32 %0, %1;" : "=f"(y) : "f"(x)); return y;
}

// ---------------------------------------------------------------------------
// init: zero h0, c0 and the t=0 output slice (out is poisoned by harness)
// ---------------------------------------------------------------------------
__global__ void k_init(float *__restrict__ out) {
    int idx = blockIdx.x * blockDim.x + threadIdx.x;
    int stride = gridDim.x * blockDim.x;
    for (int i = idx; i < Bz * Hz; i += stride) {
        g_h[0][i] = 0.f;
        g_c[i] = 0.f;
    }
    for (int i = idx; i < Bz * VTz; i += stride) {
        int bb = i / VTz, vv = i - bb * VTz;
        out[(size_t)bb * Tz * VTz + vv] = 0.f;
    }
}

// ---------------------------------------------------------------------------
// one LSTM step. Block = 256 thr / 8 warps, 32 gate-rows (4 gates x 8 j).
// Warp w owns rows 4w..4w+3; lanes = batch. Weight LDS is warp-broadcast
// (free, N=1); each per-lane x LDS.128 feeds 4 rows x 2 FMA2 (62% FMA density).
// Cell update fused in-block via smem gate exchange. grid 128 -> H=1024.
// mode 0: encoder (x = enc_emb[src[b][step]]), also writes g_enc_out
// mode 1: decoder (x = g_xin), also writes g_hall[step]
// ---------------------------------------------------------------------------
__global__ void __launch_bounds__(256) k_lstm(
    const float *__restrict__ emb, const int *__restrict__ tok,
    const float *__restrict__ Wih, const float *__restrict__ Whh,
    const float *__restrict__ bih, const float *__restrict__ bhh,
    int Kx, int par, int mode, int step) {
    __shared__ float4 xs[32 * 33];   // 32 batches x TK floats (pad 33 f4/row)
    __shared__ float4 ws[32 * 33];   // 32 gate-rows x TK floats
    __shared__ float smg[32 * 33];   // gate exchange [row][lane]
    __shared__ int stok[32];

    int tid = threadIdx.x, lane = tid & 31, w = tid >> 5;
    int j0 = blockIdx.x * 8;
    const float *hin = g_h[par];

    if (mode == 0 && tid < 32) stok[tid] = tok[tid * Sz + step];

    u64 acc[4] = {0, 0, 0, 0};
    int nt0 = Kx / TK;
    int ntot = nt0 + Hz / TK;

    for (int t = 0; t < ntot; ++t) {
        int seg = (t >= nt0);
        int koff = (seg ? (t - nt0) : t) * TK;
        int Kseg = seg ? Hz : Kx;
        const float *Wb = seg ? Whh : Wih;
        __syncthreads();
        // stage x tile: warp-iter = one batch row, coalesced
        for (int i = tid; i < 32 * 32; i += 256) {
            int bb = i >> 5, c4 = i & 31;
            const float *xp;
            if (seg) xp = hin + bb * Hz + koff;
            else if (mode == 0) xp = emb + (size_t)stok[bb] * Ez + koff;
            else xp = g_xin + bb * (Ez + Hz) + koff;
            xs[bb * 33 + c4] = *(const float4 *)(xp + c4 * 4);
        }
        // stage 32 weight rows, coalesced along k
        for (int i = tid; i < 32 * 32; i += 256) {
            int r = i >> 5, c4 = i & 31;
            int grow = (r >> 3) * Hz + j0 + (r & 7);
            ws[r * 33 + c4] = *(const float4 *)(
                Wb + (size_t)grow * Kseg + koff + c4 * 4);
        }
        __syncthreads();
        const ulonglong2 *xp2 = (const ulonglong2 *)(xs + lane * 33);
        const ulonglong2 *w0 = (const ulonglong2 *)(ws + (4 * w + 0) * 33);
        const ulonglong2 *w1 = (const ulonglong2 *)(ws + (4 * w + 1) * 33);
        const ulonglong2 *w2 = (const ulonglong2 *)(ws + (4 * w + 2) * 33);
        const ulonglong2 *w3 = (const ulonglong2 *)(ws + (4 * w + 3) * 33);
#pragma unroll
        for (int kk = 0; kk < 32; ++kk) {
            ulonglong2 xv = xp2[kk];            // per-lane x (expensive LDS)
            ulonglong2 q;
            q = w0[kk]; fma2(acc[0], xv.x, q.x); fma2(acc[0], xv.y, q.y);
            q = w1[kk]; fma2(acc[1], xv.x, q.x); fma2(acc[1], xv.y, q.y);
            q = w2[kk]; fma2(acc[2], xv.x, q.x); fma2(acc[2], xv.y, q.y);
            q = w3[kk]; fma2(acc[3], xv.x, q.x); fma2(acc[3], xv.y, q.y);
        }
    }
    // fold halves + biases, exchange gates via smem
#pragma unroll
    for (int i = 0; i < 4; ++i) {
        int r = 4 * w + i, g = r >> 3, jg = g * Hz + j0 + (r & 7);
        float2 t = up(acc[i]);
        smg[r * 33 + lane] = t.x + t.y + __ldg(bih + jg) + __ldg(bhh + jg);
    }
    __syncthreads();
    {   // thread (w=jl, lane=batch) does the cell update for j = j0 + w
        float gi = smg[(0 + w) * 33 + lane];
        float gf = smg[(8 + w) * 33 + lane];
        float gg = smg[(16 + w) * 33 + lane];
        float go = smg[(24 + w) * 33 + lane];
        int j = j0 + w;
        int idx = lane * Hz + j;
        float cn = sigf(gf) * g_c[idx] + sigf(gi) * tanhf(gg);
        g_c[idx] = cn;
        float hn = sigf(go) * tanhf(cn);
        g_h[par ^ 1][idx] = hn;
        if (mode == 0)
            g_enc_out[((size_t)lane * Sz + step) * Hz + j] = hn;
        else
            g_hall[((size_t)step * Bz + lane) * Hz + j] = hn;
    }
}

// ---------------------------------------------------------------------------
// hpart[b][j] = sum_k h[b][k] * attn_W[j][k]  (first-H half of attn_W rows)
// same broadcast-weight scheme: warp owns 2 rows, block 16 rows, grid 64
// ---------------------------------------------------------------------------
__global__ void __launch_bounds__(256) k_hpart(const float *__restrict__ attn_W, int par) {
    __shared__ float4 xs[32 * 33];
    __shared__ float4 ws[16 * 33];
    int tid = threadIdx.x, lane = tid & 31, w = tid >> 5;
    int j0 = blockIdx.x * 16;
    const float *hin = g_h[par];
    u64 acc[2] = {0, 0};

    for (int t = 0; t < Hz / TK; ++t) {
        int koff = t * TK;
        __syncthreads();
        for (int i = tid; i < 32 * 32; i += 256) {
            int bb = i >> 5, c4 = i & 31;
            xs[bb * 33 + c4] = *(const float4 *)(hin + bb * Hz + koff + c4 * 4);
        }
        for (int i = tid; i < 16 * 32; i += 256) {
            int r = i >> 5, c4 = i & 31;
            ws[r * 33 + c4] = *(const float4 *)(
                attn_W + (size_t)(j0 + r) * (2 * Hz) + koff + c4 * 4);
        }
        __syncthreads();
        const ulonglong2 *xp2 = (const ulonglong2 *)(xs + lane * 33);
        const ulonglong2 *w0 = (const ulonglong2 *)(ws + (2 * w + 0) * 33);
        const ulonglong2 *w1 = (const ulonglong2 *)(ws + (2 * w + 1) * 33);
#pragma unroll
        for (int kk = 0; kk < 32; ++kk) {
            ulonglong2 xv = xp2[kk];
            ulonglong2 q;
            q = w0[kk]; fma2(acc[0], xv.x, q.x); fma2(acc[0], xv.y, q.y);
            q = w1[kk]; fma2(acc[1], xv.x, q.x); fma2(acc[1], xv.y, q.y);
        }
    }
#pragma unroll
    for (int i = 0; i < 2; ++i) {
        float2 t = up(acc[i]);
        g_hpart[lane * Hz + j0 + 2 * w + i] = t.x + t.y;
    }
}

// ---------------------------------------------------------------------------
// scores[b][s] = sum_j tanh(hpart[b][j] + encpart[b][s][j]) * v[j]
// one warp per (b,s) pair; MUFU-pipe tanh.approx
// ---------------------------------------------------------------------------
__global__ void __launch_bounds__(256) k_score(const float *__restrict__ v) {
    int w = blockIdx.x * 8 + (threadIdx.x >> 5);
    int lane = threadIdx.x & 31;
    int b = w >> 6, s = w & 63;
    const float *ep = g_encpart + ((size_t)b * Sz + s) * Hz;
    const float *hp = g_hpart + (size_t)b * Hz;
    float acc = 0.f;
    for (int k = lane * 4; k < Hz; k += 128) {
        float4 e = *(const float4 *)(ep + k);
        float4 h = *(const float4 *)(hp + k);
        float4 vv = *(const float4 *)(v + k);
        acc += tanha(h.x + e.x) * vv.x + tanha(h.y + e.y) * vv.y +
               tanha(h.z + e.z) * vv.z + tanha(h.w + e.w) * vv.w;
    }
#pragma unroll
    for (int o = 16; o; o >>= 1) acc += __shfl_xor_sync(0xffffffffu, acc, o);
    if (lane == 0) g_scores[b * Sz + s] = acc;
}

// ---------------------------------------------------------------------------
// softmax over S, context = attn @ enc_out, xin = [dec_emb[tok] | ctx]
// one block per batch element
// ---------------------------------------------------------------------------
__global__ void __launch_bounds__(256) k_ctx(const float *__restrict__ dec_emb,
                                             const int *__restrict__ tgt, int d) {
    __shared__ float sm[64];
    int b = blockIdx.x, tid = threadIdx.x;
    if (tid < 64) sm[tid] = g_scores[b * Sz + tid];
    __syncthreads();
    if (tid == 0) {
        float m = sm[0];
        for (int i = 1; i < 64; i++) m = fmaxf(m, sm[i]);
        float ssum = 0.f;
        for (int i = 0; i < 64; i++) {
            float e = __expf(sm[i] - m);
            sm[i] = e;
            ssum += e;
        }
        float inv = 1.0f / ssum;
        for (int i = 0; i < 64; i++) sm[i] *= inv;
    }
    __syncthreads();
    const float *eb = g_enc_out + (size_t)b * Sz * Hz;
    int h0 = tid * 4;
    float4 acc = make_float4(0.f, 0.f, 0.f, 0.f);
    for (int s = 0; s < 64; s++) {
        float a = sm[s];
        float4 e = *(const float4 *)(eb + (size_t)s * Hz + h0);
        acc.x += a * e.x;
        acc.y += a * e.y;
        acc.z += a * e.z;
        acc.w += a * e.w;
    }
    *(float4 *)(g_xin + (size_t)b * (Ez + Hz) + Ez + h0) = acc;
    if (tid < Ez / 4) {
        int tk = tgt[b * Tz + d];
        *(float4 *)(g_xin + (size_t)b * (Ez + Hz) + tid * 4) =
            *(const float4 *)(dec_emb + (size_t)tk * Ez + tid * 4);
    }
}

// ---------------------------------------------------------------------------
// SGEMM (NT): C[r][n] = bias[n] + sum_k A[r][k]*Bm[n][k]
// BM=128, BN=64, BK=16, 256 thr, 8x4 micro-tile, paired-k f32x2 accumulators.
// EVEN u64 pads (134/68) keep every ulonglong2 smem access 16B-aligned
// (odd pads trap: misaligned LDS.128) while still skewing bank mapping.
// mode 0: A=g_enc_out -> g_encpart   (attention precompute)
// mode 1: A=g_hall    -> out, remapped (b, t+1, vocab)   (final fc)
// ---------------------------------------------------------------------------
#define APAD 134
#define BPAD 68
__global__ void __launch_bounds__(256) k_sgemm(
    int M, int N, int K,
    const float *__restrict__ Bm, int ldb,
    const float *__restrict__ bias,
    float *__restrict__ outp, int mode) {
    __shared__ u64 As2[8 * APAD];
    __shared__ u64 Bs2[8 * BPAD];
    const float *A = mode ? g_hall : g_enc_out;
    int tid = threadIdx.x;
    int col0 = blockIdx.x * 64, row0 = blockIdx.y * 128;
    int tn = tid & 15, tr = tid >> 4;
    // staging ids
    int ma = tid >> 2, qa = tid & 3;       // A: 64 rows x 4 f4 per pass (2 passes)
    int nb = tid >> 2, qb = tid & 3;       // B: 64 rows x 4 f4
    u64 acc[32];
#pragma unroll
    for (int i = 0; i < 32; i++) acc[i] = 0ull;

    for (int k0 = 0; k0 < K; k0 += 16) {
        __syncthreads();
#pragma unroll
        for (int p = 0; p < 2; ++p) {
            int r = row0 + ma + 64 * p;
            float4 v = make_float4(0.f, 0.f, 0.f, 0.f);
            if (r < M) v = *(const float4 *)(A + (size_t)r * Hz + k0 + qa * 4);
            As2[(2 * qa) * APAD + ma + 64 * p] = pk(v.x, v.y);
            As2[(2 * qa + 1) * APAD + ma + 64 * p] = pk(v.z, v.w);
        }
        {
            float4 u = *(const float4 *)(Bm + (size_t)(col0 + nb) * ldb + k0 + qb * 4);
            Bs2[(2 * qb) * BPAD + nb] = pk(u.x, u.y);
            Bs2[(2 * qb + 1) * BPAD + nb] = pk(u.z, u.w);
        }
        __syncthreads();
#pragma unroll
        for (int kp = 0; kp < 8; kp++) {
            u64 a2[8], b2[4];
#pragma unroll
            for (int i = 0; i < 4; i++)
                *(ulonglong2 *)&a2[2 * i] =
                    *(const ulonglong2 *)&As2[kp * APAD + tr * 8 + 2 * i];
            *(ulonglong2 *)&b2[0] = *(const ulonglong2 *)&Bs2[kp * BPAD + tn * 4];
            *(ulonglong2 *)&b2[2] = *(const ulonglong2 *)&Bs2[kp * BPAD + tn * 4 + 2];
#pragma unroll
            for (int i = 0; i < 8; i++)
#pragma unroll
                for (int jj = 0; jj < 4; jj++)
                    fma2(acc[i * 4 + jj], a2[i], b2[jj]);
        }
    }
#pragma unroll
    for (int i = 0; i < 8; i++) {
        int row = row0 + tr * 8 + i;
        if (row >= M) continue;
#pragma unroll
        for (int jj = 0; jj < 4; jj++) {
            int col = col0 + tn * 4 + jj;
            float2 t = up(acc[i * 4 + jj]);
            float val = t.x + t.y + __ldg(bias + col);
            if (mode == 0) {
                g_encpart[(size_t)row * Hz + col] = val;
            } else {
                int st = row >> 5, bb = row & 31;
                outp[((size_t)bb * Tz + (st + 1)) * VTz + col] = val;
            }
        }
    }
}

// ---------------------------------------------------------------------------
extern "C" void kernel_launch(void* const* d_in, const int* in_sizes, int n_in,
                              void* d_out, int out_size) {
    const int   *src     = (const int *)d_in[0];
    const int   *tgt     = (const int *)d_in[1];
    const float *enc_emb = (const float *)d_in[2];
    const float *enc_Wih = (const float *)d_in[3];
    const float *enc_Whh = (const float *)d_in[4];
    const float *enc_bih = (const float *)d_in[5];
    const float *enc_bhh = (const float *)d_in[6];
    const float *dec_emb = (const float *)d_in[7];
    const float *attn_W  = (const float *)d_in[8];
    const float *attn_b  = (const float *)d_in[9];
    const float *v_W     = (const float *)d_in[10];
    const float *dec_Wih = (const float *)d_in[11];
    const float *dec_Whh = (const float *)d_in[12];
    const float *dec_bih = (const float *)d_in[13];
    const float *dec_bhh = (const float *)d_in[14];
    const float *fc_W    = (const float *)d_in[15];
    const float *fc_b    = (const float *)d_in[16];
    float *out = (float *)d_out;

    k_init<<<512, 256>>>(out);

    // encoder: 64 sequential LSTM steps
    for (int s = 0; s < Sz; s++)
        k_lstm<<<128, 256>>>(enc_emb, src, enc_Wih, enc_Whh, enc_bih, enc_bhh,
                             Ez, s & 1, 0, s);

    // step-invariant attention precompute: encpart = enc_out @ Wa2^T + attn_b
    k_sgemm<<<dim3(Hz / 64, (Bz * Sz) / 128), 256>>>(
        Bz * Sz, Hz, Hz, attn_W + Hz, 2 * Hz, attn_b, nullptr, 0);

    // decoder: 63 teacher-forced steps
    for (int d = 0; d < Tz - 1; d++) {
        k_hpart<<<64, 256>>>(attn_W, d & 1);
        k_score<<<256, 256>>>(v_W);
        k_ctx<<<Bz, 256>>>(dec_emb, tgt, d);
        k_lstm<<<128, 256>>>(nullptr, nullptr, dec_Wih, dec_Whh, dec_bih,
                             dec_bhh, Ez + Hz, d & 1, 1, d);
    }

    // one big output projection: (63*32) x 32000 x 1024
    k_sgemm<<<dim3(VTz / 64, ((Tz - 1) * Bz + 127) / 128), 256>>>(
        (Tz - 1) * Bz, VTz, Hz, fc_W, Hz, fc_b, out, 1);
}

// round 17
// speedup vs baseline: 1.7028x; 1.2414x over previous
#include <cuda_runtime.h>
#include <cuda_bf16.h>
#include <cstring>

#define Bz 32
#define Sz 64
#define Tz 64
#define Ez 512
#define Hz 1024
#define VTz 32000
#define TK 128          // k-tile in floats (all K dims are multiples of 128)

// ---------------- device scratch (no dynamic alloc allowed) ----------------
__device__ float g_enc_out[Bz * Sz * Hz];     // encoder hidden states (B,S,H)
__device__ float g_encpart[Bz * Sz * Hz];     // enc_out @ Wa2^T + attn_b
__device__ float g_h[2][Bz * Hz];             // double-buffered hidden
__device__ float g_c[Bz * Hz];                // cell state (in-place safe)
__device__ float g_hpart[Bz * Hz];            // h @ Wa1^T
__device__ float g_scores[Bz * Sz];
__device__ float g_xin[Bz * (Ez + Hz)];       // decoder lstm input [emb | ctx]
__device__ float g_hall[(Tz - 1) * Bz * Hz];  // all decoder h_t for final GEMM
// K-split partials + finisher counters
__device__ float g_part[2][4 * Hz][Bz];       // lstm gate partials per k-slice
__device__ float g_hp_part[2][Hz][Bz];        // hpart partials per k-slice
__device__ unsigned int g_cnt[128];           // lstm j-group arrival counters
__device__ unsigned int g_cnt2[64];           // hpart j-group arrival counters

typedef unsigned long long u64;

// packed dual-FMA (sm_100+): 2x fp32 MAC per instruction
__device__ __forceinline__ void fma2(u64 &d, u64 a, u64 b) {
    asm("fma.rn.f32x2 %0, %1, %2, %0;" : "+l"(d) : "l"(a), "l"(b));
}
__device__ __forceinline__ float2 up(u64 v) {
    float2 t; memcpy(&t, &v, 8); return t;
}
__device__ __forceinline__ u64 pk(float x, float y) {
    float2 t = make_float2(x, y); u64 r; memcpy(&r, &t, 8); return r;
}
__device__ __forceinline__ float sigf(float x) { return 1.0f / (1.0f + __expf(-x)); }
__device__ __forceinline__ float tanha(float x) {
    float y; asm("tanh.approx.f32 %0, %1;" : "=f"(y) : "f"(x)); return y;
}

// ---------------------------------------------------------------------------
// init: zero h0, c0, counters, and the t=0 output slice (out is poisoned)
// ---------------------------------------------------------------------------
__global__ void k_init(float *__restrict__ out) {
    int idx = blockIdx.x * blockDim.x + threadIdx.x;
    int stride = gridDim.x * blockDim.x;
    for (int i = idx; i < Bz * Hz; i += stride) {
        g_h[0][i] = 0.f;
        g_c[i] = 0.f;
    }
    if (idx < 128) g_cnt[idx] = 0u;
    if (idx < 64) g_cnt2[idx] = 0u;
    for (int i = idx; i < Bz * VTz; i += stride) {
        int bb = i / VTz, vv = i - bb * VTz;
        out[(size_t)bb * Tz * VTz + vv] = 0.f;
    }
}

// ---------------------------------------------------------------------------
// one LSTM step, K-SPLIT across 2 blocks per j-group (grid 256 -> 2 blk/SM).
// Block = 256 thr / 8 warps; block covers 32 gate-rows (4 gates x 8 j) over
// HALF the k-range. Warp owns 4 rows (weight LDS broadcast = free; each
// per-lane x LDS.128 feeds 8 FMA2). Both slices store partial gate sums;
// the LAST-arriving block (per-group atomic counter) adds partner partials +
// biases and runs the fused cell update. fp-add commutes -> deterministic.
// mode 0: encoder (x = enc_emb[src[b][step]]), writes g_enc_out
// mode 1: decoder (x = g_xin), writes g_hall[step]
// ---------------------------------------------------------------------------
__global__ void __launch_bounds__(256) k_lstm(
    const float *__restrict__ emb, const int *__restrict__ tok,
    const float *__restrict__ Wih, const float *__restrict__ Whh,
    const float *__restrict__ bih, const float *__restrict__ bhh,
    int Kx, int par, int mode, int step) {
    __shared__ float4 xs[32 * 33];   // 32 batches x TK floats (pad 33 f4/row)
    __shared__ float4 ws[32 * 33];   // 32 gate-rows x TK floats
    __shared__ float smg[32 * 33];   // gate exchange [row][lane]
    __shared__ int stok[32];
    __shared__ int sfin;

    int tid = threadIdx.x, lane = tid & 31, w = tid >> 5;
    int jg = blockIdx.x >> 1, slice = blockIdx.x & 1;
    int j0 = jg * 8;
    const float *hin = g_h[par];

    if (mode == 0 && tid < 32) stok[tid] = tok[tid * Sz + step];

    u64 acc[4] = {0, 0, 0, 0};
    int nt0 = Kx / TK;
    int ntot = nt0 + Hz / TK;        // enc 12, dec 20 (both even)
    int half = ntot >> 1;
    int t1 = slice * half + half;

    for (int t = slice * half; t < t1; ++t) {
        int seg = (t >= nt0);
        int koff = (seg ? (t - nt0) : t) * TK;
        int Kseg = seg ? Hz : Kx;
        const float *Wb = seg ? Whh : Wih;
        __syncthreads();
        // stage x tile: warp-iter = one batch row, coalesced
        for (int i = tid; i < 32 * 32; i += 256) {
            int bb = i >> 5, c4 = i & 31;
            const float *xp;
            if (seg) xp = hin + bb * Hz + koff;
            else if (mode == 0) xp = emb + (size_t)stok[bb] * Ez + koff;
            else xp = g_xin + bb * (Ez + Hz) + koff;
            xs[bb * 33 + c4] = *(const float4 *)(xp + c4 * 4);
        }
        // stage 32 weight rows, coalesced along k
        for (int i = tid; i < 32 * 32; i += 256) {
            int r = i >> 5, c4 = i & 31;
            int grow = (r >> 3) * Hz + j0 + (r & 7);
            ws[r * 33 + c4] = *(const float4 *)(
                Wb + (size_t)grow * Kseg + koff + c4 * 4);
        }
        __syncthreads();
        const ulonglong2 *xp2 = (const ulonglong2 *)(xs + lane * 33);
        const ulonglong2 *w0 = (const ulonglong2 *)(ws + (4 * w + 0) * 33);
        const ulonglong2 *w1 = (const ulonglong2 *)(ws + (4 * w + 1) * 33);
        const ulonglong2 *w2 = (const ulonglong2 *)(ws + (4 * w + 2) * 33);
        const ulonglong2 *w3 = (const ulonglong2 *)(ws + (4 * w + 3) * 33);
#pragma unroll
        for (int kk = 0; kk < 32; kk += 2) {
            // batched loads first (stretch load-use distance), then FMAs
            ulonglong2 xv0 = xp2[kk], xv1 = xp2[kk + 1];
            ulonglong2 q00 = w0[kk], q01 = w0[kk + 1];
            ulonglong2 q10 = w1[kk], q11 = w1[kk + 1];
            ulonglong2 q20 = w2[kk], q21 = w2[kk + 1];
            ulonglong2 q30 = w3[kk], q31 = w3[kk + 1];
            fma2(acc[0], xv0.x, q00.x); fma2(acc[0], xv0.y, q00.y);
            fma2(acc[1], xv0.x, q10.x); fma2(acc[1], xv0.y, q10.y);
            fma2(acc[2], xv0.x, q20.x); fma2(acc[2], xv0.y, q20.y);
            fma2(acc[3], xv0.x, q30.x); fma2(acc[3], xv0.y, q30.y);
            fma2(acc[0], xv1.x, q01.x); fma2(acc[0], xv1.y, q01.y);
            fma2(acc[1], xv1.x, q11.x); fma2(acc[1], xv1.y, q11.y);
            fma2(acc[2], xv1.x, q21.x); fma2(acc[2], xv1.y, q21.y);
            fma2(acc[3], xv1.x, q31.x); fma2(acc[3], xv1.y, q31.y);
        }
    }
    // publish this slice's partial gate sums
#pragma unroll
    for (int i = 0; i < 4; ++i) {
        int r = 4 * w + i;
        int grow = (r >> 3) * Hz + j0 + (r & 7);
        float2 tt = up(acc[i]);
        g_part[slice][grow][lane] = tt.x + tt.y;
    }
    __threadfence();
    __syncthreads();
    if (tid == 0) sfin = (atomicAdd(&g_cnt[jg], 1u) == 1u);
    __syncthreads();
    if (!sfin) return;

    // finisher: own(regs) + partner(gmem) + biases -> gate exchange
    __threadfence();
#pragma unroll
    for (int i = 0; i < 4; ++i) {
        int r = 4 * w + i;
        int grow = (r >> 3) * Hz + j0 + (r & 7);
        float2 tt = up(acc[i]);
        smg[r * 33 + lane] = (tt.x + tt.y) + g_part[slice ^ 1][grow][lane] +
                             __ldg(bih + grow) + __ldg(bhh + grow);
    }
    __syncthreads();
    if (tid == 0) g_cnt[jg] = 0u;    // reset for next step
    {   // thread (w=jl, lane=batch) does the cell update for j = j0 + w
        float gi = smg[(0 + w) * 33 + lane];
        float gf = smg[(8 + w) * 33 + lane];
        float gg = smg[(16 + w) * 33 + lane];
        float go = smg[(24 + w) * 33 + lane];
        int j = j0 + w;
        int idx = lane * Hz + j;
        float cn = sigf(gf) * g_c[idx] + sigf(gi) * tanhf(gg);
        g_c[idx] = cn;
        float hn = sigf(go) * tanhf(cn);
        g_h[par ^ 1][idx] = hn;
        if (mode == 0)
            g_enc_out[((size_t)lane * Sz + step) * Hz + j] = hn;
        else
            g_hall[((size_t)step * Bz + lane) * Hz + j] = hn;
    }
}

// ---------------------------------------------------------------------------
// hpart[b][j] = sum_k h[b][k] * attn_W[j][k]  (first-H half of attn_W rows)
// K-split x2 like k_lstm: grid 128 = 64 groups x 2 slices; block 16 rows
// (8 warps x 2 rows); finisher sums both halves and stores.
// ---------------------------------------------------------------------------
__global__ void __launch_bounds__(256) k_hpart(const float *__restrict__ attn_W, int par) {
    __shared__ float4 xs[32 * 33];
    __shared__ float4 ws[16 * 33];
    __shared__ int sfin;
    int tid = threadIdx.x, lane = tid & 31, w = tid >> 5;
    int jg = blockIdx.x >> 1, slice = blockIdx.x & 1;
    int j0 = jg * 16;
    const float *hin = g_h[par];
    u64 acc[2] = {0, 0};

    int half = (Hz / TK) >> 1;       // 4 tiles per slice
    int t1 = slice * half + half;
    for (int t = slice * half; t < t1; ++t) {
        int koff = t * TK;
        __syncthreads();
        for (int i = tid; i < 32 * 32; i += 256) {
            int bb = i >> 5, c4 = i & 31;
            xs[bb * 33 + c4] = *(const float4 *)(hin + bb * Hz + koff + c4 * 4);
        }
        for (int i = tid; i < 16 * 32; i += 256) {
            int r = i >> 5, c4 = i & 31;
            ws[r * 33 + c4] = *(const float4 *)(
                attn_W + (size_t)(j0 + r) * (2 * Hz) + koff + c4 * 4);
        }
        __syncthreads();
        const ulonglong2 *xp2 = (const ulonglong2 *)(xs + lane * 33);
        const ulonglong2 *w0 = (const ulonglong2 *)(ws + (2 * w + 0) * 33);
        const ulonglong2 *w1 = (const ulonglong2 *)(ws + (2 * w + 1) * 33);
#pragma unroll
        for (int kk = 0; kk < 32; kk += 2) {
            ulonglong2 xv0 = xp2[kk], xv1 = xp2[kk + 1];
            ulonglong2 q00 = w0[kk], q01 = w0[kk + 1];
            ulonglong2 q10 = w1[kk], q11 = w1[kk + 1];
            fma2(acc[0], xv0.x, q00.x); fma2(acc[0], xv0.y, q00.y);
            fma2(acc[1], xv0.x, q10.x); fma2(acc[1], xv0.y, q10.y);
            fma2(acc[0], xv1.x, q01.x); fma2(acc[0], xv1.y, q01.y);
            fma2(acc[1], xv1.x, q11.x); fma2(acc[1], xv1.y, q11.y);
        }
    }
#pragma unroll
    for (int i = 0; i < 2; ++i) {
        float2 t = up(acc[i]);
        g_hp_part[slice][j0 + 2 * w + i][lane] = t.x + t.y;
    }
    __threadfence();
    __syncthreads();
    if (tid == 0) sfin = (atomicAdd(&g_cnt2[jg], 1u) == 1u);
    __syncthreads();
    if (!sfin) return;
    __threadfence();
#pragma unroll
    for (int i = 0; i < 2; ++i) {
        int j = j0 + 2 * w + i;
        float2 t = up(acc[i]);
        g_hpart[lane * Hz + j] = (t.x + t.y) + g_hp_part[slice ^ 1][j][lane];
    }
    if (tid == 0) g_cnt2[jg] = 0u;
}

// ---------------------------------------------------------------------------
// scores[b][s] = sum_j tanh(hpart[b][j] + encpart[b][s][j]) * v[j]
// one warp per (b,s) pair; MUFU-pipe tanh.approx
// ---------------------------------------------------------------------------
__global__ void __launch_bounds__(256) k_score(const float *__restrict__ v) {
    int w = blockIdx.x * 8 + (threadIdx.x >> 5);
    int lane = threadIdx.x & 31;
    int b = w >> 6, s = w & 63;
    const float *ep = g_encpart + ((size_t)b * Sz + s) * Hz;
    const float *hp = g_hpart + (size_t)b * Hz;
    float acc = 0.f;
    for (int k = lane * 4; k < Hz; k += 128) {
        float4 e = *(const float4 *)(ep + k);
        float4 h = *(const float4 *)(hp + k);
        float4 vv = *(const float4 *)(v + k);
        acc += tanha(h.x + e.x) * vv.x + tanha(h.y + e.y) * vv.y +
               tanha(h.z + e.z) * vv.z + tanha(h.w + e.w) * vv.w;
    }
#pragma unroll
    for (int o = 16; o; o >>= 1) acc += __shfl_xor_sync(0xffffffffu, acc, o);
    if (lane == 0) g_scores[b * Sz + s] = acc;
}

// ---------------------------------------------------------------------------
// softmax over S, context = attn @ enc_out, xin = [dec_emb[tok] | ctx]
// one block per batch element
// ---------------------------------------------------------------------------
__global__ void __launch_bounds__(256) k_ctx(const float *__restrict__ dec_emb,
                                             const int *__restrict__ tgt, int d) {
    __shared__ float sm[64];
    int b = blockIdx.x, tid = threadIdx.x;
    if (tid < 64) sm[tid] = g_scores[b * Sz + tid];
    __syncthreads();
    if (tid == 0) {
        float m = sm[0];
        for (int i = 1; i < 64; i++) m = fmaxf(m, sm[i]);
        float ssum = 0.f;
        for (int i = 0; i < 64; i++) {
            float e = __expf(sm[i] - m);
            sm[i] = e;
            ssum += e;
        }
        float inv = 1.0f / ssum;
        for (int i = 0; i < 64; i++) sm[i] *= inv;
    }
    __syncthreads();
    const float *eb = g_enc_out + (size_t)b * Sz * Hz;
    int h0 = tid * 4;
    float4 acc = make_float4(0.f, 0.f, 0.f, 0.f);
    for (int s = 0; s < 64; s++) {
        float a = sm[s];
        float4 e = *(const float4 *)(eb + (size_t)s * Hz + h0);
        acc.x += a * e.x;
        acc.y += a * e.y;
        acc.z += a * e.z;
        acc.w += a * e.w;
    }
    *(float4 *)(g_xin + (size_t)b * (Ez + Hz) + Ez + h0) = acc;
    if (tid < Ez / 4) {
        int tk = tgt[b * Tz + d];
        *(float4 *)(g_xin + (size_t)b * (Ez + Hz) + tid * 4) =
            *(const float4 *)(dec_emb + (size_t)tk * Ez + tid * 4);
    }
}

// ---------------------------------------------------------------------------
// SGEMM (NT): C[r][n] = bias[n] + sum_k A[r][k]*Bm[n][k]
// BM=128, BN=64, BK=16, 256 thr, 8x4 micro-tile, paired-k f32x2 accumulators.
// EVEN u64 pads (134/68) keep every ulonglong2 smem access 16B-aligned.
// mode 0: A=g_enc_out -> g_encpart   (attention precompute)
// mode 1: A=g_hall    -> out, remapped (b, t+1, vocab)   (final fc)
// ---------------------------------------------------------------------------
#define APAD 134
#define BPAD 68
__global__ void __launch_bounds__(256) k_sgemm(
    int M, int N, int K,
    const float *__restrict__ Bm, int ldb,
    const float *__restrict__ bias,
    float *__restrict__ outp, int mode) {
    __shared__ u64 As2[8 * APAD];
    __shared__ u64 Bs2[8 * BPAD];
    const float *A = mode ? g_hall : g_enc_out;
    int tid = threadIdx.x;
    int col0 = blockIdx.x * 64, row0 = blockIdx.y * 128;
    int tn = tid & 15, tr = tid >> 4;
    int ma = tid >> 2, qa = tid & 3;
    int nb = tid >> 2, qb = tid & 3;
    u64 acc[32];
#pragma unroll
    for (int i = 0; i < 32; i++) acc[i] = 0ull;

    for (int k0 = 0; k0 < K; k0 += 16) {
        __syncthreads();
#pragma unroll
        for (int p = 0; p < 2; ++p) {
            int r = row0 + ma + 64 * p;
            float4 v = make_float4(0.f, 0.f, 0.f, 0.f);
            if (r < M) v = *(const float4 *)(A + (size_t)r * Hz + k0 + qa * 4);
            As2[(2 * qa) * APAD + ma + 64 * p] = pk(v.x, v.y);
            As2[(2 * qa + 1) * APAD + ma + 64 * p] = pk(v.z, v.w);
        }
        {
            float4 u = *(const float4 *)(Bm + (size_t)(col0 + nb) * ldb + k0 + qb * 4);
            Bs2[(2 * qb) * BPAD + nb] = pk(u.x, u.y);
            Bs2[(2 * qb + 1) * BPAD + nb] = pk(u.z, u.w);
        }
        __syncthreads();
#pragma unroll
        for (int kp = 0; kp < 8; kp++) {
            u64 a2[8], b2[4];
#pragma unroll
            for (int i = 0; i < 4; i++)
                *(ulonglong2 *)&a2[2 * i] =
                    *(const ulonglong2 *)&As2[kp * APAD + tr * 8 + 2 * i];
            *(ulonglong2 *)&b2[0] = *(const ulonglong2 *)&Bs2[kp * BPAD + tn * 4];
            *(ulonglong2 *)&b2[2] = *(const ulonglong2 *)&Bs2[kp * BPAD + tn * 4 + 2];
#pragma unroll
            for (int i = 0; i < 8; i++)
#pragma unroll
                for (int jj = 0; jj < 4; jj++)
                    fma2(acc[i * 4 + jj], a2[i], b2[jj]);
        }
    }
#pragma unroll
    for (int i = 0; i < 8; i++) {
        int row = row0 + tr * 8 + i;
        if (row >= M) continue;
#pragma unroll
        for (int jj = 0; jj < 4; jj++) {
            int col = col0 + tn * 4 + jj;
            float2 t = up(acc[i * 4 + jj]);
            float val = t.x + t.y + __ldg(bias + col);
            if (mode == 0) {
                g_encpart[(size_t)row * Hz + col] = val;
            } else {
                int st = row >> 5, bb = row & 31;
                outp[((size_t)bb * Tz + (st + 1)) * VTz + col] = val;
            }
        }
    }
}

// ---------------------------------------------------------------------------
extern "C" void kernel_launch(void* const* d_in, const int* in_sizes, int n_in,
                              void* d_out, int out_size) {
    const int   *src     = (const int *)d_in[0];
    const int   *tgt     = (const int *)d_in[1];
    const float *enc_emb = (const float *)d_in[2];
    const float *enc_Wih = (const float *)d_in[3];
    const float *enc_Whh = (const float *)d_in[4];
    const float *enc_bih = (const float *)d_in[5];
    const float *enc_bhh = (const float *)d_in[6];
    const float *dec_emb = (const float *)d_in[7];
    const float *attn_W  = (const float *)d_in[8];
    const float *attn_b  = (const float *)d_in[9];
    const float *v_W     = (const float *)d_in[10];
    const float *dec_Wih = (const float *)d_in[11];
    const float *dec_Whh = (const float *)d_in[12];
    const float *dec_bih = (const float *)d_in[13];
    const float *dec_bhh = (const float *)d_in[14];
    const float *fc_W    = (const float *)d_in[15];
    const float *fc_b    = (const float *)d_in[16];
    float *out = (float *)d_out;

    k_init<<<512, 256>>>(out);

    // encoder: 64 sequential LSTM steps (grid 256 = 128 j-groups x 2 k-slices)
    for (int s = 0; s < Sz; s++)
        k_lstm<<<256, 256>>>(enc_emb, src, enc_Wih, enc_Whh, enc_bih, enc_bhh,
                             Ez, s & 1, 0, s);

    // step-invariant attention precompute: encpart = enc_out @ Wa2^T + attn_b
    k_sgemm<<<dim3(Hz / 64, (Bz * Sz) / 128), 256>>>(
        Bz * Sz, Hz, Hz, attn_W + Hz, 2 * Hz, attn_b, nullptr, 0);

    // decoder: 63 teacher-forced steps
    for (int d = 0; d < Tz - 1; d++) {
        k_hpart<<<128, 256>>>(attn_W, d & 1);
        k_score<<<256, 256>>>(v_W);
        k_ctx<<<Bz, 256>>>(dec_emb, tgt, d);
        k_lstm<<<256, 256>>>(nullptr, nullptr, dec_Wih, dec_Whh, dec_bih,
                             dec_bhh, Ez + Hz, d & 1, 1, d);
    }

    // one big output projection: (63*32) x 32000 x 1024
    k_sgemm<<<dim3(VTz / 64, ((Tz - 1) * Bz + 127) / 128), 256>>>(
        (Tz - 1) * Bz, VTz, Hz, fc_W, Hz, fc_b, out, 1);
}